// round 16
// baseline (speedup 1.0000x reference)
#include <cuda_runtime.h>
#include <cuda_bf16.h>
#include <cstdint>

// Problem shape (fixed by the dataset)
#define B_ 8
#define T_ 4096
#define F_ 512
#define ROWS_ (B_ * T_)

#define NZBLK 2048                   // zero-fill blocks in k_zero_scan
#define NSBLK B_                     // scan blocks in k_zero_scan

// Scratch (no allocations allowed) — device globals.
__device__ float g_z[ROWS_];        // linear scores (monotone-equiv. for peaks)
__device__ int   g_idx[ROWS_];      // per batch: compact list of peak t's
__device__ int   g_hlens[B_];       // peak counts per batch

// ---------------------------------------------------------------------------
// Kernel 1: pure GEMV read stream. 256 blocks x 512 threads (one wave at
// 2 CTA/SM). Each warp does 8 rows in two 4-row batches (16 LDG.128 each).
// Triggers programmatic launch completion immediately so k_zero_scan's
// zero-fill blocks overlap with the read stream.
__global__ void __launch_bounds__(512) k_gemv(const float* __restrict__ feat,
                                              const float* __restrict__ W) {
    cudaTriggerProgrammaticLaunchCompletion();

    const int lane = threadIdx.x & 31;
    const int wid  = threadIdx.x >> 5;         // 0..15

    const float4* w4 = reinterpret_cast<const float4*>(W);
    float4 wreg[4];
#pragma unroll
    for (int i = 0; i < 4; i++) wreg[i] = w4[lane + i * 32];

    const int base = blockIdx.x * 128 + wid * 8;
#pragma unroll
    for (int it = 0; it < 2; it++) {
        const int row0 = base + it * 4;
        const float4* f0 = reinterpret_cast<const float4*>(feat + (size_t)(row0 + 0) * F_);
        const float4* f1 = reinterpret_cast<const float4*>(feat + (size_t)(row0 + 1) * F_);
        const float4* f2 = reinterpret_cast<const float4*>(feat + (size_t)(row0 + 2) * F_);
        const float4* f3 = reinterpret_cast<const float4*>(feat + (size_t)(row0 + 3) * F_);

        float4 a[4][4];
#pragma unroll
        for (int i = 0; i < 4; i++) {
            const int idx = lane + i * 32;
            a[0][i] = f0[idx];
            a[1][i] = f1[idx];
            a[2][i] = f2[idx];
            a[3][i] = f3[idx];
        }
        float s0 = 0.f, s1 = 0.f, s2 = 0.f, s3 = 0.f;
#pragma unroll
        for (int i = 0; i < 4; i++) {
            const float4 w = wreg[i];
            s0 += a[0][i].x * w.x + a[0][i].y * w.y + a[0][i].z * w.z + a[0][i].w * w.w;
            s1 += a[1][i].x * w.x + a[1][i].y * w.y + a[1][i].z * w.z + a[1][i].w * w.w;
            s2 += a[2][i].x * w.x + a[2][i].y * w.y + a[2][i].z * w.z + a[2][i].w * w.w;
            s3 += a[3][i].x * w.x + a[3][i].y * w.y + a[3][i].z * w.z + a[3][i].w * w.w;
        }
#pragma unroll
        for (int o = 16; o > 0; o >>= 1) {
            s0 += __shfl_down_sync(0xFFFFFFFFu, s0, o);
            s1 += __shfl_down_sync(0xFFFFFFFFu, s1, o);
            s2 += __shfl_down_sync(0xFFFFFFFFu, s2, o);
            s3 += __shfl_down_sync(0xFFFFFFFFu, s3, o);
        }
        if (lane == 0) {
            g_z[row0 + 0] = s0;
            g_z[row0 + 1] = s1;
            g_z[row0 + 2] = s2;
            g_z[row0 + 3] = s3;
        }
    }
}

// ---------------------------------------------------------------------------
// Kernel 2 (PDL secondary): blocks 0..NZBLK-1 zero-fill the output WITHOUT
// waiting (overlaps k_gemv's reads); blocks NZBLK.. wait for k_gemv via
// cudaGridDependencySynchronize, then peak-detect + scan their batch into a
// compact gather list.
__global__ void __launch_bounds__(512) k_zero_scan(float* __restrict__ out,
                                                   int out_size) {
    const int bid = blockIdx.x;
    const int tid = threadIdx.x;

    if (bid < NZBLK) {
        // Zero 16 output rows = 2048 float4; 512 threads x 4 float4.
        float4* d = reinterpret_cast<float4*>(out) + (size_t)bid * 2048;
        const float4 z4 = make_float4(0.f, 0.f, 0.f, 0.f);
#pragma unroll
        for (int i = 0; i < 4; i++)
            d[tid + i * 512] = z4;
        return;
    }

    // ---- scan blocks: true dependency on k_gemv ----
    cudaGridDependencySynchronize();

    const int b    = bid - NZBLK;              // 0..7
    const int lane = tid & 31;
    const int wid  = tid >> 5;                 // 0..15

    __shared__ int warp_sums[16];
    __shared__ int warp_incl[16];

    const float* zb = g_z + b * T_;
    const int t0 = tid * 8;                    // 512 * 8 = 4096

    int flags[8];
    int cnt = 0;
#pragma unroll
    for (int k = 0; k < 8; k++) {
        int t = t0 + k;
        float c = zb[t];
        float l = (t > 0)      ? zb[t - 1] : c;
        float r = (t < T_ - 1) ? zb[t + 1] : c;
        flags[k] = (c >= l) & (c >= r);
        cnt += flags[k];
    }

    int v = cnt;
#pragma unroll
    for (int o = 1; o < 32; o <<= 1) {
        int n = __shfl_up_sync(0xFFFFFFFFu, v, o);
        if (lane >= o) v += n;
    }
    if (lane == 31) warp_sums[wid] = v;
    __syncthreads();
    if (wid == 0 && lane < 16) {
        int s = warp_sums[lane];
#pragma unroll
        for (int o = 1; o < 16; o <<= 1) {
            int n = __shfl_up_sync(0x0000FFFFu, s, o);
            if (lane >= o) s += n;
        }
        warp_incl[lane] = s;
    }
    __syncthreads();

    int excl = (v - cnt) + (wid > 0 ? warp_incl[wid - 1] : 0);
#pragma unroll
    for (int k = 0; k < 8; k++) {
        int t = t0 + k;
        if (flags[k]) g_idx[b * T_ + excl] = t;    // i-th peak is position t
        excl += flags[k];
    }
    if (tid == 0) {
        int hl = warp_incl[15];
        g_hlens[b] = hl;
        if (out_size >= ROWS_ * F_ + B_)
            out[(size_t)ROWS_ * F_ + b] = (float)hl;
    }
}

// ---------------------------------------------------------------------------
// Kernel 3: copy peak rows only (tail already zeroed by kernel 2; stream
// order guarantees zeros and scan are complete). Dest-centric: 128-thread
// group per dest row; i < hl[b] -> copy feat row g_idx[b][i] (L2-resident).
__global__ void __launch_bounds__(512) k_copy(const float* __restrict__ feat,
                                              float* __restrict__ out) {
    const int tid = threadIdx.x;
    __shared__ int s_hl[B_];
    if (tid < B_) s_hl[tid] = g_hlens[tid];
    __syncthreads();

    const int row = blockIdx.x * 4 + (tid >> 7);   // dest row
    const int j   = tid & 127;                     // float4 index within row
    const int b   = row >> 12;                     // T_ = 4096
    const int i   = row & (T_ - 1);

    if (i < s_hl[b]) {
        const int src = b * T_ + g_idx[row];
        const float4 v = reinterpret_cast<const float4*>(feat + (size_t)src * F_)[j];
        reinterpret_cast<float4*>(out + (size_t)row * F_)[j] = v;
    }
}

extern "C" void kernel_launch(void* const* d_in, const int* in_sizes, int n_in,
                              void* d_out, int out_size) {
    const float* feat = (const float*)d_in[0];
    const float* W    = (const float*)d_in[1];
    float* out        = (float*)d_out;

    // 1) GEMV (triggers PDL completion early)
    k_gemv<<<ROWS_ / 128, 512>>>(feat, W);

    // 2) zero-fill + scan, launched with programmatic stream serialization so
    //    its zero blocks overlap k_gemv.
    {
        cudaLaunchAttribute attr[1];
        attr[0].id = cudaLaunchAttributeProgrammaticStreamSerialization;
        attr[0].val.programmaticStreamSerializationAllowed = 1;

        cudaLaunchConfig_t cfg = {};
        cfg.gridDim  = dim3(NZBLK + NSBLK, 1, 1);
        cfg.blockDim = dim3(512, 1, 1);
        cfg.dynamicSmemBytes = 0;
        cfg.stream = 0;                        // legacy default stream (captured)
        cfg.attrs = attr;
        cfg.numAttrs = 1;

        cudaLaunchKernelEx(&cfg, k_zero_scan, out, out_size);
    }

    // 3) copy peak rows (normal stream order: after zeros + scan complete)
    k_copy<<<ROWS_ / 4, 512>>>(feat, out);
}

// round 17
// speedup vs baseline: 1.0621x; 1.0621x over previous
#include <cuda_runtime.h>
#include <cuda_bf16.h>
#include <cstdint>

// Problem shape (fixed by the dataset)
#define B_ 8
#define T_ 4096
#define F_ 512
#define ROWS_ (B_ * T_)

#define GRID_ 148          // 1 CTA per SM; all co-resident
#define BLK_  1024

// Scratch (no allocations allowed) — device globals.
__device__ float g_z[ROWS_];        // linear scores (monotone-equiv. for peaks)
__device__ int   g_idx[ROWS_];      // per batch: compact list of peak t's
__device__ int   g_hlens[B_];       // peak counts per batch
__device__ unsigned g_bar_count = 0;
__device__ unsigned g_bar_gen   = 0;

// Software grid barrier (all 148 CTAs co-resident at 1 CTA/SM).
__device__ __forceinline__ void grid_barrier() {
    __syncthreads();
    if (threadIdx.x == 0) {
        unsigned gen = *(volatile unsigned*)&g_bar_gen;
        __threadfence();                       // publish this block's phase writes
        unsigned arr = atomicAdd(&g_bar_count, 1u);
        if (arr == GRID_ - 1) {
            atomicExch(&g_bar_count, 0u);
            __threadfence();
            atomicAdd(&g_bar_gen, 1u);         // release
        } else {
            while (*(volatile unsigned*)&g_bar_gen == gen) { }
        }
        __threadfence();                       // acquire other blocks' writes
    }
    __syncthreads();
}

__global__ void __launch_bounds__(BLK_, 1)
k_fused(const float* __restrict__ feat, const float* __restrict__ W,
        float* __restrict__ out, int out_size) {
    const int tid  = threadIdx.x;
    const int lane = tid & 31;
    const int wid  = tid >> 5;                 // 0..31
    const int bid  = blockIdx.x;

    __shared__ int warp_sums[32];
    __shared__ int warp_incl[32];
    __shared__ int s_hl[B_];

    // ------------------------------------------------------------------
    // Phase 1: pure GEMV. feat loads use __ldcs (evict-first) so feat does
    // NOT occupy L2 at normal priority — the L2 capacity is reserved for
    // absorbing phase-3's output writes, which then drain lazily into the
    // next graph replay's read phase instead of stalling this one.
    // FOUR rows per warp per iteration: 16 independent LDG.128 in flight.
    {
        const float4* w4 = reinterpret_cast<const float4*>(W);
        float4 wreg[4];
#pragma unroll
        for (int i = 0; i < 4; i++) wreg[i] = w4[lane + i * 32];

        for (int row0 = bid * 128 + wid * 4; row0 < ROWS_; row0 += GRID_ * 128) {
            const float4* f0 = reinterpret_cast<const float4*>(feat + (size_t)(row0 + 0) * F_);
            const float4* f1 = reinterpret_cast<const float4*>(feat + (size_t)(row0 + 1) * F_);
            const float4* f2 = reinterpret_cast<const float4*>(feat + (size_t)(row0 + 2) * F_);
            const float4* f3 = reinterpret_cast<const float4*>(feat + (size_t)(row0 + 3) * F_);
            float s0 = 0.f, s1 = 0.f, s2 = 0.f, s3 = 0.f;
#pragma unroll
            for (int i = 0; i < 4; i++) {
                const int idx = lane + i * 32;
                const float4 w = wreg[i];
                float4 a0 = __ldcs(&f0[idx]);
                float4 a1 = __ldcs(&f1[idx]);
                float4 a2 = __ldcs(&f2[idx]);
                float4 a3 = __ldcs(&f3[idx]);
                s0 += a0.x * w.x + a0.y * w.y + a0.z * w.z + a0.w * w.w;
                s1 += a1.x * w.x + a1.y * w.y + a1.z * w.z + a1.w * w.w;
                s2 += a2.x * w.x + a2.y * w.y + a2.z * w.z + a2.w * w.w;
                s3 += a3.x * w.x + a3.y * w.y + a3.z * w.z + a3.w * w.w;
            }
#pragma unroll
            for (int o = 16; o > 0; o >>= 1) {
                s0 += __shfl_down_sync(0xFFFFFFFFu, s0, o);
                s1 += __shfl_down_sync(0xFFFFFFFFu, s1, o);
                s2 += __shfl_down_sync(0xFFFFFFFFu, s2, o);
                s3 += __shfl_down_sync(0xFFFFFFFFu, s3, o);
            }
            if (lane == 0) {
                g_z[row0 + 0] = s0;
                g_z[row0 + 1] = s1;
                g_z[row0 + 2] = s2;
                g_z[row0 + 3] = s3;
            }
        }
    }

    grid_barrier();

    // ------------------------------------------------------------------
    // Phase 2: blocks 0..7 — peak detect + compact gather list per batch.
    if (bid < B_) {
        const int b = bid;
        const float* zb = g_z + b * T_;
        const int t0 = tid * 4;                // 1024 threads * 4 = 4096

        int flags[4];
        int cnt = 0;
#pragma unroll
        for (int k = 0; k < 4; k++) {
            int t = t0 + k;
            float c = zb[t];
            float l = (t > 0)      ? zb[t - 1] : c;
            float r = (t < T_ - 1) ? zb[t + 1] : c;
            flags[k] = (c >= l) & (c >= r);
            cnt += flags[k];
        }

        int v = cnt;
#pragma unroll
        for (int o = 1; o < 32; o <<= 1) {
            int n = __shfl_up_sync(0xFFFFFFFFu, v, o);
            if (lane >= o) v += n;
        }
        if (lane == 31) warp_sums[wid] = v;
        __syncthreads();
        if (wid == 0) {
            int s = warp_sums[lane];
#pragma unroll
            for (int o = 1; o < 32; o <<= 1) {
                int n = __shfl_up_sync(0xFFFFFFFFu, s, o);
                if (lane >= o) s += n;
            }
            warp_incl[lane] = s;
        }
        __syncthreads();

        int excl = (v - cnt) + (wid > 0 ? warp_incl[wid - 1] : 0);
#pragma unroll
        for (int k = 0; k < 4; k++) {
            int t = t0 + k;
            if (flags[k]) g_idx[b * T_ + excl] = t;   // compact: i-th peak is t
            excl += flags[k];
        }
        if (tid == 0) {
            int hl = warp_incl[31];
            g_hlens[b] = hl;
            if (out_size >= ROWS_ * F_ + B_)
                out[(size_t)ROWS_ * F_ + b] = (float)hl;
        }
    }

    grid_barrier();

    // ------------------------------------------------------------------
    // Phase 3: destination-centric writer. Each output row (b, i) written
    // exactly once: i < hl[b] -> copy feat row g_idx[b][i], else zero.
    // Gather loads are __ldcs (last use of feat); output stores are PLAIN
    // write-back so the L2 absorbs them (they drain lazily, off the
    // critical path). Coalesced sequential writes.
    {
        if (tid < B_) s_hl[tid] = g_hlens[tid];
        __syncthreads();

        const int sub = tid >> 7;              // 0..7: group id
        const int j   = tid & 127;             // float4 index within row
        const float4 z4 = make_float4(0.f, 0.f, 0.f, 0.f);

        for (int base = bid * 32 + sub * 4; base < ROWS_; base += GRID_ * 32) {
            int src[4];
#pragma unroll
            for (int k = 0; k < 4; k++) {
                const int row = base + k;
                const int b = row >> 12;       // T_ = 4096
                const int i = row & (T_ - 1);
                src[k] = (i < s_hl[b]) ? (b * T_ + g_idx[row]) : -1;
            }
            float4 v4[4];
#pragma unroll
            for (int k = 0; k < 4; k++)
                v4[k] = (src[k] >= 0)
                    ? __ldcs(&reinterpret_cast<const float4*>(feat + (size_t)src[k] * F_)[j])
                    : z4;
#pragma unroll
            for (int k = 0; k < 4; k++)
                reinterpret_cast<float4*>(out + (size_t)(base + k) * F_)[j] = v4[k];
        }
    }
}

extern "C" void kernel_launch(void* const* d_in, const int* in_sizes, int n_in,
                              void* d_out, int out_size) {
    const float* feat = (const float*)d_in[0];
    const float* W    = (const float*)d_in[1];
    float* out        = (float*)d_out;
    k_fused<<<GRID_, BLK_>>>(feat, W, out, out_size);
}